// round 1
// baseline (speedup 1.0000x reference)
#include <cuda_runtime.h>

#define A_    32
#define B_    32
#define KK_   9
#define KKA_  288
#define PS_   16
#define OH_   7
#define OW_   7
#define L_    49
#define NW_   8     // warps per block
#define NT_   256

// lam values: 0.01*(1-0.95^(i+1))
__device__ __constant__ float c_lam[3] = {0.0005f, 0.000975f, 0.00142625f};

__device__ __forceinline__ float4 vrow(float4 p, float4 w0, float4 w1, float4 w2, float4 w3) {
    float4 v;
    v.x = fmaf(p.x, w0.x, fmaf(p.y, w1.x, fmaf(p.z, w2.x, p.w * w3.x)));
    v.y = fmaf(p.x, w0.y, fmaf(p.y, w1.y, fmaf(p.z, w2.y, p.w * w3.y)));
    v.z = fmaf(p.x, w0.z, fmaf(p.y, w1.z, fmaf(p.z, w2.z, p.w * w3.z)));
    v.w = fmaf(p.x, w0.w, fmaf(p.y, w1.w, fmaf(p.z, w2.w, p.w * w3.w)));
    return v;
}

__device__ __forceinline__ float accrow(float4 v, float4 m, float4 is, float acc) {
    float d;
    d = v.x - m.x; acc = fmaf(d * is.x, d, acc);
    d = v.y - m.y; acc = fmaf(d * is.y, d, acc);
    d = v.z - m.z; acc = fmaf(d * is.z, d, acc);
    d = v.w - m.w; acc = fmaf(d * is.w, d, acc);
    return acc;
}

__device__ __forceinline__ void acc4(float* a1, float* a2, float ra, float4 v) {
    float t;
    t = ra * v.x; a1[0] += t; a2[0] = fmaf(t, v.x, a2[0]);
    t = ra * v.y; a1[1] += t; a2[1] = fmaf(t, v.y, a2[1]);
    t = ra * v.z; a1[2] += t; a2[2] = fmaf(t, v.z, a2[2]);
    t = ra * v.w; a1[3] += t; a2[3] = fmaf(t, v.w, a2[3]);
}

__global__ void __launch_bounds__(NT_)
convcaps_kernel(const float* __restrict__ a_in,
                const float* __restrict__ pose,
                const float* __restrict__ Wg,
                const float* __restrict__ beta_u,
                const float* __restrict__ beta_a,
                float* __restrict__ out,
                int batch)
{
    __shared__ __align__(16) float pose_s[KKA_][PS_];   // [n][i*4+m]
    __shared__ float au_s[KKA_];
    __shared__ float S1s[PS_][B_];                      // [j][o]
    __shared__ float S2s[PS_][B_];
    __shared__ float rss[B_];
    __shared__ __align__(16) float mu4s[4][B_][4];      // [j>>2][o][j&3]
    __shared__ __align__(16) float i2s4s[4][B_][4];     // 1/(2*sigma)
    __shared__ float lsg[PS_][B_];                      // log(sigma)
    __shared__ float lnS_s[B_];                         // sum_j log(sigma*LN_2PI)
    __shared__ float lna_s[B_];                         // log(a_out)

    const int site = blockIdx.x;
    const int bb = site / L_;
    const int l  = site - bb * L_;
    const int oy = l / OW_, ox = l - oy * OW_;
    const int tid = threadIdx.x;
    const int wid = tid >> 5, lane = tid & 31;
    const int aout_total = batch * B_ * L_;

    // ---- load pose window (288 x 16) and activations (288) into smem ----
    // n = p*32 + a, p = ki*3+kj ; pose_s[n][s] = pose[bb][a*16+s][2oy+ki][2ox+kj]
    for (int idx = tid; idx < KKA_ * PS_; idx += NT_) {
        int n = idx >> 4, s = idx & 15;
        int p = n >> 5, a = n & 31;
        int ki = p / 3, kj = p - 3 * ki;
        pose_s[n][s] = pose[((bb * 512 + a * 16 + s) * 16 + 2 * oy + ki) * 16 + 2 * ox + kj];
    }
    for (int n = tid; n < KKA_; n += NT_) {
        int p = n >> 5, a = n & 31;
        int ki = p / 3, kj = p - 3 * ki;
        au_s[n] = a_in[((bb * 32 + a) * 16 + 2 * oy + ki) * 16 + 2 * ox + kj];
    }
    __syncthreads();

    const float4* __restrict__ Wv = (const float4*)Wg;

    for (int it = 0; it < 3; ++it) {
        // zero accumulators
        for (int idx = tid; idx < PS_ * B_; idx += NT_) {
            ((float*)S1s)[idx] = 0.0f;
            ((float*)S2s)[idx] = 0.0f;
        }
        if (tid < B_) rss[tid] = 0.0f;
        __syncthreads();

        // ---- accumulation pass: each warp strides over n, lane = o ----
        float a1[PS_], a2[PS_];
        float rs = 0.0f;
        #pragma unroll
        for (int k = 0; k < PS_; ++k) { a1[k] = 0.0f; a2[k] = 0.0f; }

        float4 mu[4], is2[4];
        float lnS = 0.0f, lna = 0.0f;
        if (it > 0) {
            const float4* m4 = (const float4*)mu4s;
            const float4* i4 = (const float4*)i2s4s;
            #pragma unroll
            for (int g = 0; g < 4; ++g) { mu[g] = m4[g * 32 + lane]; is2[g] = i4[g * 32 + lane]; }
            lnS = lnS_s[lane];
            lna = lna_s[lane];
        }

        for (int n = wid; n < KKA_; n += NW_) {
            const float4* pr = (const float4*)pose_s[n];
            float4 p0 = pr[0], p1 = pr[1], p2 = pr[2], p3 = pr[3];
            const float4* wp = Wv + ((n * B_ + lane) << 2);
            float4 w0 = wp[0], w1 = wp[1], w2 = wp[2], w3 = wp[3];
            float4 v0 = vrow(p0, w0, w1, w2, w3);
            float4 v1 = vrow(p1, w0, w1, w2, w3);
            float4 v2 = vrow(p2, w0, w1, w2, w3);
            float4 v3 = vrow(p3, w0, w1, w2, w3);

            float r;
            if (it > 0) {
                float acc = 0.0f;
                acc = accrow(v0, mu[0], is2[0], acc);
                acc = accrow(v1, mu[1], is2[1], acc);
                acc = accrow(v2, mu[2], is2[2], acc);
                acc = accrow(v3, mu[3], is2[3], acc);
                float t = fmaf(-0.5f, lnS, lna) - acc;   // ln_p + log(a)
                float m = t;
                #pragma unroll
                for (int d = 16; d; d >>= 1)
                    m = fmaxf(m, __shfl_xor_sync(0xffffffffu, m, d));
                float e = __expf(t - m);
                float ssum = e;
                #pragma unroll
                for (int d = 16; d; d >>= 1)
                    ssum += __shfl_xor_sync(0xffffffffu, ssum, d);
                r = e / ssum;
            } else {
                r = 1.0f;
            }
            float ra = r * au_s[n];
            rs += ra;
            acc4(a1 + 0,  a2 + 0,  ra, v0);
            acc4(a1 + 4,  a2 + 4,  ra, v1);
            acc4(a1 + 8,  a2 + 8,  ra, v2);
            acc4(a1 + 12, a2 + 12, ra, v3);
        }

        #pragma unroll
        for (int k = 0; k < PS_; ++k) {
            atomicAdd(&S1s[k][lane], a1[k]);
            atomicAdd(&S2s[k][lane], a2[k]);
        }
        atomicAdd(&rss[lane], rs);
        __syncthreads();

        // ---- stage 2a: per (o,j) stats ----
        const bool last = (it == 2);
        for (int idx = tid; idx < PS_ * B_; idx += NT_) {
            int j = idx >> 5, o = idx & 31;
            float denom = rss[o] + 1e-12f;
            float m = S1s[j][o] / denom;
            float e2 = S2s[j][o] / denom;
            float sig = fmaxf(e2 - m * m, 0.0f) + 1e-12f;
            lsg[j][o] = __logf(sig);
            mu4s[j >> 2][o][j & 3]  = m;
            i2s4s[j >> 2][o][j & 3] = 0.5f / sig;
            if (last) {
                // pose_out[bb][o*16+j][oy][ox]
                out[aout_total + ((bb * 512 + o * 16 + j) * OH_ + oy) * OW_ + ox] = m;
            }
        }
        __syncthreads();

        // ---- stage 2b: per-o activation ----
        if (tid < B_) {
            int o = tid;
            float SL = 0.0f;
            #pragma unroll
            for (int j = 0; j < PS_; ++j) SL += lsg[j][o];
            float cost = rss[o] * (16.0f * beta_u[o] + 0.5f * SL);
            float x = c_lam[it] * (beta_a[o] - cost);
            float a = 1.0f / (1.0f + __expf(-x));
            if (it == 2) {
                out[((bb * B_ + o) * OH_ + oy) * OW_ + ox] = a;
            } else {
                lna_s[o] = __logf(a);
                // sum_j log(sigma*LN_2PI) = SL + 16*log(LN_2PI)
                lnS_s[o] = SL + 16.0f * logf(1.8378770664093453f);
            }
        }
        __syncthreads();
    }
}

extern "C" void kernel_launch(void* const* d_in, const int* in_sizes, int n_in,
                              void* d_out, int out_size) {
    const float* a_in  = (const float*)d_in[0];
    const float* pose  = (const float*)d_in[1];
    const float* Wg    = (const float*)d_in[2];
    const float* bu    = (const float*)d_in[3];
    const float* ba    = (const float*)d_in[4];
    float* out = (float*)d_out;

    int batch = in_sizes[0] / (A_ * 16 * 16);   // 8
    int grid = batch * L_;                       // 392
    convcaps_kernel<<<grid, NT_>>>(a_in, pose, Wg, bu, ba, out, batch);
}